// round 4
// baseline (speedup 1.0000x reference)
#include <cuda_runtime.h>
#include <cuda_bf16.h>
#include <cstdint>

// Problem constants (fixed by the reference)
constexpr int B_   = 32;
constexpr int C_   = 3;
constexpr int H_   = 512;
constexpr int W_   = 512;
constexpr int OH_  = 128;
constexpr int OW_  = 64;
constexpr int NNZ_ = 98304;

constexpr int HW_   = H_ * W_;          // 262144
constexpr int CHW_  = C_ * HW_;         // 786432  (per-sample x stride)
constexpr int OHW_  = OH_ * OW_;        // 8192
constexpr int COHW_ = C_ * OHW_;        // 24576   (per-sample out stride)
constexpr int RES_  = B_ * COHW_;       // 786432  (result element count)
constexpr int E_    = B_ * NNZ_;        // 3145728 total COO entries (fits int)

constexpr int TPB  = 256;
constexpr int EPT  = 4;                 // entries per thread per iteration
constexpr int NBLK = 152 * 8;           // persistent: GB300 has 152 SMs, 8 CTAs/SM

__global__ void __launch_bounds__(TPB, 8)   // cap regs at 32 -> 8 CTAs/SM guaranteed
tti_persist_kernel(const float* __restrict__ x,
                   const int*   __restrict__ rows,
                   const int*   __restrict__ cols,
                   const float* __restrict__ vals,
                   const float* __restrict__ mask,
                   float*       __restrict__ out,
                   int mask_elems)
{
    const int tid    = blockIdx.x * TPB + threadIdx.x;
    const int stride = gridDim.x * TPB * EPT;

    // ---- persistent grid-stride scatter ----
    // Each thread handles 4 consecutive entries; chunks are 4-aligned and
    // NNZ%4==0, so a chunk never straddles a sample boundary.
    for (int base = tid * EPT; base < E_; base += stride) {
        const int b = base / NNZ_;      // sample id (const-div -> IMAD.HI)

        const int4   c4 = *reinterpret_cast<const int4*>(cols + base);
        const int4   r4 = *reinterpret_cast<const int4*>(rows + base);
        const float4 v4 = *reinterpret_cast<const float4*>(vals + base);

        const float* __restrict__ xb = x + (long)b * CHW_;
        float*       __restrict__ ob = out + (long)b * COHW_;

        const int   cc[EPT] = {c4.x, c4.y, c4.z, c4.w};
        const int   rr[EPT] = {r4.x, r4.y, r4.z, r4.w};
        const float vv[EPT] = {v4.x, v4.y, v4.z, v4.w};

        // Issue all gathers before any atomic (per-thread MLP=4).
        float g[EPT];
#pragma unroll
        for (int i = 0; i < EPT; ++i) {
            const int col = cc[i];
            const int hw  = col / 3;        // spatial index (h*W + w)
            const int ch  = col - 3 * hw;   // channel
            g[i] = __ldg(xb + ch * HW_ + hw);
        }

        // Fire-and-forget REDG scatter (avg 4 dups per address over 786K).
#pragma unroll
        for (int i = 0; i < EPT; ++i) {
            const int row = rr[i];
            const int p   = row / 3;        // oh*OW + ow
            const int rc  = row - 3 * p;    // channel
            atomicAdd(ob + rc * OHW_ + p, vv[i] * g[i]);
        }
    }

    // ---- mask pass-through epilogue (independent of scatter results) ----
    const float4* __restrict__ m4 = reinterpret_cast<const float4*>(mask);
    float4* __restrict__       o4 = reinterpret_cast<float4*>(out + RES_);
    const int total4  = mask_elems >> 2;
    const int stride1 = gridDim.x * TPB;
    for (int i = tid; i < total4; i += stride1)
        o4[i] = m4[i];
}

extern "C" void kernel_launch(void* const* d_in, const int* in_sizes, int n_in,
                              void* d_out, int out_size)
{
    const float* x    = (const float*)d_in[0];
    const int*   rows = (const int*)  d_in[1];
    const int*   cols = (const int*)  d_in[2];
    const float* vals = (const float*)d_in[3];
    const float* mask = (const float*)d_in[4];
    float* out = (float*)d_out;

    // Node 1: zero the result region (atomics accumulate; out is poisoned).
    cudaMemsetAsync(out, 0, (size_t)RES_ * sizeof(float), 0);

    // Node 2: persistent fused scatter + mask copy.
    const int mask_elems = out_size - RES_;   // = 786432
    tti_persist_kernel<<<NBLK, TPB>>>(x, rows, cols, vals, mask, out, mask_elems);
}

// round 5
// speedup vs baseline: 1.0027x; 1.0027x over previous
#include <cuda_runtime.h>
#include <cuda_bf16.h>
#include <cstdint>

// Problem constants (fixed by the reference)
constexpr int B_   = 32;
constexpr int C_   = 3;
constexpr int H_   = 512;
constexpr int W_   = 512;
constexpr int OH_  = 128;
constexpr int OW_  = 64;
constexpr int NNZ_ = 98304;

constexpr int HW_   = H_ * W_;          // 262144
constexpr int CHW_  = C_ * HW_;         // 786432  (per-sample x stride)
constexpr int OHW_  = OH_ * OW_;        // 8192
constexpr int COHW_ = C_ * OHW_;        // 24576   (per-sample out stride)
constexpr int RES_  = B_ * COHW_;       // 786432  (result element count)
constexpr int E_    = B_ * NNZ_;        // 3145728 total COO entries

constexpr int TPB   = 256;
constexpr int EPT   = 4;
constexpr int NBLK  = 1024;                    // 1024*256*4*3 == E_ exactly
constexpr int ITERS = 3;
constexpr int STRIDE = NBLK * TPB * EPT;       // 1048576 entries per iteration

static_assert((long)NBLK * TPB * EPT * ITERS == (long)E_, "exact tiling");

__global__ void __launch_bounds__(TPB, 7)      // 7 CTAs/SM * 152 SMs = 1064 >= 1024: one wave
tti_pipe_kernel(const float* __restrict__ x,
                const int*   __restrict__ rows,
                const int*   __restrict__ cols,
                const float* __restrict__ vals,
                const float* __restrict__ mask,
                float*       __restrict__ out,
                int mask_elems)
{
    const int tid  = blockIdx.x * TPB + threadIdx.x;
    int base = tid * EPT;

    // Prologue: fetch iteration-0 indices.
    int4 c4 = *reinterpret_cast<const int4*>(cols + base);
    int4 r4 = *reinterpret_cast<const int4*>(rows + base);

#pragma unroll
    for (int it = 0; it < ITERS; ++it) {
        // Value load overlaps the idx-load wait (independent).
        const float4 v4 = *reinterpret_cast<const float4*>(vals + base);

        const int b = base / NNZ_;              // chunk never straddles a sample
        const float* __restrict__ xb = x + (long)b * CHW_;
        float*       __restrict__ ob = out + (long)b * COHW_;

        const int cc[EPT] = {c4.x, c4.y, c4.z, c4.w};
        const int rr[EPT] = {r4.x, r4.y, r4.z, r4.w};

        // Issue all gathers (depend on c4).
        float g[EPT];
#pragma unroll
        for (int i = 0; i < EPT; ++i) {
            const int col = cc[i];
            const int hw  = col / 3;            // spatial index (h*W + w)
            const int ch  = col - 3 * hw;       // channel
            g[i] = __ldg(xb + ch * HW_ + hw);
        }

        // Software pipeline: prefetch next iteration's indices while the
        // gathers above are still in flight (hides the idx-load latency).
        const int nbase = base + STRIDE;
        if (it + 1 < ITERS) {
            c4 = *reinterpret_cast<const int4*>(cols + nbase);
            r4 = *reinterpret_cast<const int4*>(rows + nbase);
        }

        // REDG scatter (fire-and-forget; avg 4 dups/address over 786K).
        const float vv[EPT] = {v4.x, v4.y, v4.z, v4.w};
#pragma unroll
        for (int i = 0; i < EPT; ++i) {
            const int row = rr[i];
            const int p   = row / 3;            // oh*OW + ow
            const int rc  = row - 3 * p;        // channel
            atomicAdd(ob + rc * OHW_ + p, vv[i] * g[i]);
        }

        base = nbase;
    }

    // ---- mask pass-through epilogue (independent of scatter results) ----
    const float4* __restrict__ m4 = reinterpret_cast<const float4*>(mask);
    float4* __restrict__       o4 = reinterpret_cast<float4*>(out + RES_);
    const int total4 = mask_elems >> 2;
    const int gs     = NBLK * TPB;
    for (int i = tid; i < total4; i += gs)
        o4[i] = m4[i];
}

extern "C" void kernel_launch(void* const* d_in, const int* in_sizes, int n_in,
                              void* d_out, int out_size)
{
    const float* x    = (const float*)d_in[0];
    const int*   rows = (const int*)  d_in[1];
    const int*   cols = (const int*)  d_in[2];
    const float* vals = (const float*)d_in[3];
    const float* mask = (const float*)d_in[4];
    float* out = (float*)d_out;

    // Node 1: zero the result region (atomics accumulate; out is poisoned).
    cudaMemsetAsync(out, 0, (size_t)RES_ * sizeof(float), 0);

    // Node 2: one-wave pipelined scatter + mask copy.
    const int mask_elems = out_size - RES_;     // = 786432
    tti_pipe_kernel<<<NBLK, TPB>>>(x, rows, cols, vals, mask, out, mask_elems);
}

// round 6
// speedup vs baseline: 1.0410x; 1.0381x over previous
#include <cuda_runtime.h>
#include <cuda_bf16.h>
#include <cstdint>

// Problem constants (fixed by the reference)
constexpr int B_   = 32;
constexpr int C_   = 3;
constexpr int H_   = 512;
constexpr int W_   = 512;
constexpr int OH_  = 128;
constexpr int OW_  = 64;
constexpr int NNZ_ = 98304;

constexpr int HW_   = H_ * W_;          // 262144
constexpr int CHW_  = C_ * HW_;         // 786432  (per-sample x stride)
constexpr int OHW_  = OH_ * OW_;        // 8192
constexpr int COHW_ = C_ * OHW_;        // 24576   (per-sample out stride)
constexpr int RES_  = B_ * COHW_;       // 786432  (result element count)

constexpr int TPB   = 128;                        // small CTAs: fine-grain scheduling
constexpr int EPT   = 4;
constexpr int GRIDX = NNZ_ / (TPB * EPT);         // 192 CTAs per sample

__global__ void __launch_bounds__(TPB)
tti_fused_kernel(const float* __restrict__ x,
                 const int*   __restrict__ rows,
                 const int*   __restrict__ cols,
                 const float* __restrict__ vals,
                 const float* __restrict__ mask,
                 float*       __restrict__ out,
                 int mask_elems)
{
    const int b = blockIdx.y;

    if (b == B_) {
        // ---- mask pass-through plane (independent of the scatter work) ----
        const float4* __restrict__ m4 = reinterpret_cast<const float4*>(mask);
        float4* __restrict__       o4 = reinterpret_cast<float4*>(out + RES_);
        const int total4 = mask_elems >> 2;
        const int stride = GRIDX * TPB;
        for (int i = blockIdx.x * TPB + threadIdx.x; i < total4; i += stride)
            o4[i] = m4[i];
        return;
    }

    // ---- scatter plane ----
    const int  k    = (blockIdx.x * TPB + threadIdx.x) * EPT;
    const long base = (long)b * NNZ_ + k;

    const int4   c4 = *reinterpret_cast<const int4*>(cols + base);
    const int4   r4 = *reinterpret_cast<const int4*>(rows + base);
    const float4 v4 = *reinterpret_cast<const float4*>(vals + base);

    const float* __restrict__ xb = x + (long)b * CHW_;
    float*       __restrict__ ob = out + (long)b * COHW_;

    const int   cc[EPT] = {c4.x, c4.y, c4.z, c4.w};
    const int   rr[EPT] = {r4.x, r4.y, r4.z, r4.w};
    const float vv[EPT] = {v4.x, v4.y, v4.z, v4.w};

    // Issue all gathers before any atomic (per-thread MLP=4; chip-level MLP
    // from up to 64 resident warps/SM + CTA churn overlapping iterations).
    float g[EPT];
#pragma unroll
    for (int i = 0; i < EPT; ++i) {
        const int col = cc[i];
        const int hw  = col / 3;            // spatial index (h*W + w)
        const int ch  = col - 3 * hw;       // channel
        g[i] = __ldg(xb + ch * HW_ + hw);
    }

    // Fire-and-forget REDG scatter (avg 4 dups/address over 786K addresses).
#pragma unroll
    for (int i = 0; i < EPT; ++i) {
        const int row = rr[i];
        const int p   = row / 3;            // oh*OW + ow
        const int rc  = row - 3 * p;        // channel
        atomicAdd(ob + rc * OHW_ + p, vv[i] * g[i]);
    }
}

extern "C" void kernel_launch(void* const* d_in, const int* in_sizes, int n_in,
                              void* d_out, int out_size)
{
    const float* x    = (const float*)d_in[0];
    const int*   rows = (const int*)  d_in[1];
    const int*   cols = (const int*)  d_in[2];
    const float* vals = (const float*)d_in[3];
    const float* mask = (const float*)d_in[4];
    float* out = (float*)d_out;

    // Node 1: zero the result region (atomics accumulate; out is poisoned).
    cudaMemsetAsync(out, 0, (size_t)RES_ * sizeof(float), 0);

    // Node 2: fused scatter + mask copy, fine-grained 128-thread CTAs.
    const int mask_elems = out_size - RES_;   // = 786432
    dim3 grid(GRIDX, B_ + 1);
    tti_fused_kernel<<<grid, TPB>>>(x, rows, cols, vals, mask, out, mask_elems);
}

// round 8
// speedup vs baseline: 1.0581x; 1.0165x over previous
#include <cuda_runtime.h>
#include <cuda_bf16.h>
#include <cstdint>

// Problem constants (fixed by the reference)
constexpr int B_   = 32;
constexpr int C_   = 3;
constexpr int H_   = 512;
constexpr int W_   = 512;
constexpr int OH_  = 128;
constexpr int OW_  = 64;
constexpr int NNZ_ = 98304;

constexpr int HW_   = H_ * W_;          // 262144
constexpr int CHW_  = C_ * HW_;         // 786432  (per-sample x stride)
constexpr int OHW_  = OH_ * OW_;        // 8192
constexpr int COHW_ = C_ * OHW_;        // 24576   (per-sample out stride)
constexpr int RES_  = B_ * COHW_;       // 786432  (result element count)

constexpr int TPB   = 128;
constexpr int EPT   = 4;
constexpr int GRIDX = NNZ_ / (TPB * EPT);         // 192 CTAs per sample

// ---- cache-policy helpers (createpolicy + L2::cache_hint loads) ----
__device__ __forceinline__ uint64_t make_policy_keep() {
    uint64_t pol;
    asm("createpolicy.fractional.L2::evict_last.b64 %0, 1.0;" : "=l"(pol));
    return pol;
}
__device__ __forceinline__ uint64_t make_policy_stream() {
    uint64_t pol;
    asm("createpolicy.fractional.L2::evict_first.b64 %0, 1.0;" : "=l"(pol));
    return pol;
}
__device__ __forceinline__ float ldg_hint(const float* p, uint64_t pol) {
    float v;
    asm volatile("ld.global.nc.L2::cache_hint.f32 %0, [%1], %2;"
                 : "=f"(v) : "l"(p), "l"(pol));
    return v;
}
__device__ __forceinline__ int4 ldg_hint_i4(const int* p, uint64_t pol) {
    int4 v;
    asm volatile("ld.global.nc.L2::cache_hint.v4.s32 {%0,%1,%2,%3}, [%4], %5;"
                 : "=r"(v.x), "=r"(v.y), "=r"(v.z), "=r"(v.w) : "l"(p), "l"(pol));
    return v;
}
__device__ __forceinline__ float4 ldg_hint_f4(const float* p, uint64_t pol) {
    float4 v;
    asm volatile("ld.global.nc.L2::cache_hint.v4.f32 {%0,%1,%2,%3}, [%4], %5;"
                 : "=f"(v.x), "=f"(v.y), "=f"(v.z), "=f"(v.w) : "l"(p), "l"(pol));
    return v;
}

__global__ void __launch_bounds__(TPB)
tti_fused_kernel(const float* __restrict__ x,
                 const int*   __restrict__ rows,
                 const int*   __restrict__ cols,
                 const float* __restrict__ vals,
                 const float* __restrict__ mask,
                 float*       __restrict__ out,
                 int mask_elems)
{
    const int b = blockIdx.y;

    if (b == B_) {
        // ---- mask pass-through plane ----
        const uint64_t pstream = make_policy_stream();
        float4* __restrict__ o4 = reinterpret_cast<float4*>(out + RES_);
        const int total4 = mask_elems >> 2;
        const int stride = GRIDX * TPB;
        for (int i = blockIdx.x * TPB + threadIdx.x; i < total4; i += stride)
            o4[i] = ldg_hint_f4(mask + 4 * i, pstream);
        return;
    }

    // ---- scatter plane (shape identical to R6) ----
    const uint64_t pstream = make_policy_stream();
    const uint64_t pkeep   = make_policy_keep();

    const int  k    = (blockIdx.x * TPB + threadIdx.x) * EPT;
    const long base = (long)b * NNZ_ + k;

    const int4   c4 = ldg_hint_i4(cols + base, pstream);
    const int4   r4 = ldg_hint_i4(rows + base, pstream);
    const float4 v4 = ldg_hint_f4(vals + base, pstream);

    const float* __restrict__ xb = x + (long)b * CHW_;
    float*       __restrict__ ob = out + (long)b * COHW_;

    const int   cc[EPT] = {c4.x, c4.y, c4.z, c4.w};
    const int   rr[EPT] = {r4.x, r4.y, r4.z, r4.w};
    const float vv[EPT] = {v4.x, v4.y, v4.z, v4.w};

    // Issue all gathers before any atomic (MLP=4); x sectors pinned
    // evict-last so their ~1.58x duplicate touches hit L2.
    float g[EPT];
#pragma unroll
    for (int i = 0; i < EPT; ++i) {
        const int col = cc[i];
        const int hw  = col / 3;            // spatial index (h*W + w)
        const int ch  = col - 3 * hw;       // channel
        g[i] = ldg_hint(xb + ch * HW_ + hw, pkeep);
    }

    // Fire-and-forget REDG scatter (avg 4 dups/address over 786K addresses).
#pragma unroll
    for (int i = 0; i < EPT; ++i) {
        const int row = rr[i];
        const int p   = row / 3;            // oh*OW + ow
        const int rc  = row - 3 * p;        // channel
        atomicAdd(ob + rc * OHW_ + p, vv[i] * g[i]);
    }
}

extern "C" void kernel_launch(void* const* d_in, const int* in_sizes, int n_in,
                              void* d_out, int out_size)
{
    const float* x    = (const float*)d_in[0];
    const int*   rows = (const int*)  d_in[1];
    const int*   cols = (const int*)  d_in[2];
    const float* vals = (const float*)d_in[3];
    const float* mask = (const float*)d_in[4];
    float* out = (float*)d_out;

    // Node 1: zero the result region (atomics accumulate; out is poisoned).
    cudaMemsetAsync(out, 0, (size_t)RES_ * sizeof(float), 0);

    // Node 2: fused scatter + mask copy.
    const int mask_elems = out_size - RES_;   // = 786432
    dim3 grid(GRIDX, B_ + 1);
    tti_fused_kernel<<<grid, TPB>>>(x, rows, cols, vals, mask, out, mask_elems);
}

// round 9
// speedup vs baseline: 1.0838x; 1.0243x over previous
#include <cuda_runtime.h>
#include <cuda_bf16.h>
#include <cstdint>

// Problem constants (fixed by the reference)
constexpr int B_   = 32;
constexpr int C_   = 3;
constexpr int H_   = 512;
constexpr int W_   = 512;
constexpr int OH_  = 128;
constexpr int OW_  = 64;
constexpr int NNZ_ = 98304;

constexpr int HW_   = H_ * W_;          // 262144
constexpr int CHW_  = C_ * HW_;         // 786432  (per-sample x stride)
constexpr int OHW_  = OH_ * OW_;        // 8192
constexpr int COHW_ = C_ * OHW_;        // 24576   (per-sample out stride)
constexpr int RES_  = B_ * COHW_;       // 786432  (result element count)

constexpr int TPB   = 128;
constexpr int EPT   = 4;
constexpr int GRIDX = NNZ_ / (TPB * EPT);         // 192 CTAs per sample

// ---- cache-policy helpers ----
__device__ __forceinline__ uint64_t make_policy_keep() {
    uint64_t pol;
    asm("createpolicy.fractional.L2::evict_last.b64 %0, 1.0;" : "=l"(pol));
    return pol;
}
__device__ __forceinline__ uint64_t make_policy_stream() {
    uint64_t pol;
    asm("createpolicy.fractional.L2::evict_first.b64 %0, 1.0;" : "=l"(pol));
    return pol;
}
__device__ __forceinline__ float ldg_hint(const float* p, uint64_t pol) {
    float v;
    asm volatile("ld.global.nc.L2::cache_hint.f32 %0, [%1], %2;"
                 : "=f"(v) : "l"(p), "l"(pol));
    return v;
}
__device__ __forceinline__ int4 ldg_hint_i4(const int* p, uint64_t pol) {
    int4 v;
    asm volatile("ld.global.nc.L2::cache_hint.v4.s32 {%0,%1,%2,%3}, [%4], %5;"
                 : "=r"(v.x), "=r"(v.y), "=r"(v.z), "=r"(v.w) : "l"(p), "l"(pol));
    return v;
}
__device__ __forceinline__ float4 ldg_hint_f4(const float* p, uint64_t pol) {
    float4 v;
    asm volatile("ld.global.nc.L2::cache_hint.v4.f32 {%0,%1,%2,%3}, [%4], %5;"
                 : "=f"(v.x), "=f"(v.y), "=f"(v.z), "=f"(v.w) : "l"(p), "l"(pol));
    return v;
}
// No-return global reduction with evict_last policy: output lines are touched
// ~4x each within a sample's time window — keep them L2-resident.
__device__ __forceinline__ void red_add_hint(float* p, float v, uint64_t pol) {
    asm volatile("red.global.L2::cache_hint.add.f32 [%0], %1, %2;"
                 :: "l"(p), "f"(v), "l"(pol) : "memory");
}

__global__ void __launch_bounds__(TPB)
tti_fused_kernel(const float* __restrict__ x,
                 const int*   __restrict__ rows,
                 const int*   __restrict__ cols,
                 const float* __restrict__ vals,
                 const float* __restrict__ mask,
                 float*       __restrict__ out,
                 int mask_elems)
{
    const int b = blockIdx.y;

    if (b == B_) {
        // ---- mask pass-through plane ----
        const uint64_t pstream = make_policy_stream();
        float4* __restrict__ o4 = reinterpret_cast<float4*>(out + RES_);
        const int total4 = mask_elems >> 2;
        const int stride = GRIDX * TPB;
        for (int i = blockIdx.x * TPB + threadIdx.x; i < total4; i += stride)
            o4[i] = ldg_hint_f4(mask + 4 * i, pstream);
        return;
    }

    // ---- scatter plane (shape frozen at R8) ----
    const uint64_t pstream = make_policy_stream();
    const uint64_t pkeep   = make_policy_keep();

    const int  k    = (blockIdx.x * TPB + threadIdx.x) * EPT;
    const long base = (long)b * NNZ_ + k;

    const int4   c4 = ldg_hint_i4(cols + base, pstream);
    const int4   r4 = ldg_hint_i4(rows + base, pstream);
    const float4 v4 = ldg_hint_f4(vals + base, pstream);

    const float* __restrict__ xb = x + (long)b * CHW_;
    float*       __restrict__ ob = out + (long)b * COHW_;

    const int   cc[EPT] = {c4.x, c4.y, c4.z, c4.w};
    const int   rr[EPT] = {r4.x, r4.y, r4.z, r4.w};
    const float vv[EPT] = {v4.x, v4.y, v4.z, v4.w};

    // Issue all gathers before any atomic (MLP=4); x sectors evict-last.
    float g[EPT];
#pragma unroll
    for (int i = 0; i < EPT; ++i) {
        const int col = cc[i];
        const int hw  = col / 3;            // spatial index (h*W + w)
        const int ch  = col - 3 * hw;       // channel
        g[i] = ldg_hint(xb + ch * HW_ + hw, pkeep);
    }

    // Fire-and-forget RED scatter, output lines pinned evict_last.
#pragma unroll
    for (int i = 0; i < EPT; ++i) {
        const int row = rr[i];
        const int p   = row / 3;            // oh*OW + ow
        const int rc  = row - 3 * p;        // channel
        red_add_hint(ob + rc * OHW_ + p, vv[i] * g[i], pkeep);
    }
}

extern "C" void kernel_launch(void* const* d_in, const int* in_sizes, int n_in,
                              void* d_out, int out_size)
{
    const float* x    = (const float*)d_in[0];
    const int*   rows = (const int*)  d_in[1];
    const int*   cols = (const int*)  d_in[2];
    const float* vals = (const float*)d_in[3];
    const float* mask = (const float*)d_in[4];
    float* out = (float*)d_out;

    // Node 1: zero the result region (atomics accumulate; out is poisoned).
    cudaMemsetAsync(out, 0, (size_t)RES_ * sizeof(float), 0);

    // Node 2: fused scatter + mask copy.
    const int mask_elems = out_size - RES_;   // = 786432
    dim3 grid(GRIDX, B_ + 1);
    tti_fused_kernel<<<grid, TPB>>>(x, rows, cols, vals, mask, out, mask_elems);
}